// round 4
// baseline (speedup 1.0000x reference)
#include <cuda_runtime.h>
#include <cstddef>

#define N_NODES 50000
#define N_EDGES 800000
#define N_GRAPHS 64
#define IN_C 256
#define HID 256
#define HID2 128
#define N_DCS 64

// ---------------- static device scratch (no allocations allowed) ----------------
__device__ float g_h1[(size_t)N_NODES * HID];    // (x@W1)*dis[row]
__device__ float g_bx[(size_t)N_NODES * HID];    // relu layer1 output
__device__ float g_h2[(size_t)N_NODES * HID2];   // (bx@W2)*dis[row]
__device__ float g_cx[(size_t)N_NODES * HID2];   // relu layer2 output
__device__ float g_dis[N_NODES];
__device__ int   g_deg[N_NODES];
__device__ int   g_off[N_NODES + 1];
__device__ int   g_pos[N_NODES];
__device__ int   g_csr[N_EDGES];
__device__ int   g_gs[N_GRAPHS + 1];
__device__ float g_px[N_GRAPHS * HID2];

// ---------------- graph preprocessing ----------------
__global__ void zero_deg_kernel(int n) {
    int i = blockIdx.x * blockDim.x + threadIdx.x;
    if (i < n) g_deg[i] = 0;
}

__global__ void hist_kernel(const int* __restrict__ dst, int e) {
    int i = blockIdx.x * blockDim.x + threadIdx.x;
    if (i < e) atomicAdd(&g_deg[dst[i]], 1);
}

__global__ void dis_kernel(int n) {
    int i = blockIdx.x * blockDim.x + threadIdx.x;
    if (i < n) g_dis[i] = rsqrtf((float)g_deg[i] + 1.0f);
}

// single-block exclusive scan over g_deg -> g_off  (n up to 50000)
__global__ void scan_kernel(int n) {
    __shared__ int sh[1024];
    __shared__ int carry_s;
    int tid = threadIdx.x;
    if (tid == 0) carry_s = 0;
    __syncthreads();
    for (int base = 0; base < n; base += 1024) {
        int i = base + tid;
        int v = (i < n) ? g_deg[i] : 0;
        sh[tid] = v;
        __syncthreads();
        #pragma unroll
        for (int s = 1; s < 1024; s <<= 1) {
            int t = (tid >= s) ? sh[tid - s] : 0;
            __syncthreads();
            sh[tid] += t;
            __syncthreads();
        }
        int incl = sh[tid];
        int c0 = carry_s;
        if (i < n) g_off[i] = c0 + incl - v;   // exclusive
        __syncthreads();
        if (tid == 0) carry_s = c0 + sh[1023];
        __syncthreads();
    }
    if (tid == 0) g_off[n] = carry_s;
}

__global__ void copy_pos_kernel(int n) {
    int i = blockIdx.x * blockDim.x + threadIdx.x;
    if (i < n) g_pos[i] = g_off[i];
}

__global__ void scatter_kernel(const int* __restrict__ src, const int* __restrict__ dst, int e) {
    int i = blockIdx.x * blockDim.x + threadIdx.x;
    if (i < e) {
        int d = dst[i];
        int p = atomicAdd(&g_pos[d], 1);
        g_csr[p] = src[i];
    }
}

// ---------------- SGEMM: C[r][c] = (A[r,:] @ B[:,c]) * g_dis[r] ----------------
// A: [M,K] row-major, B: [K,N] row-major. N % 128 == 0, K % 8 == 0, M guarded.
#define BM 128
#define BN 128
#define BK 8
__global__ __launch_bounds__(256) void sgemm_scaled_kernel(
    const float* __restrict__ A, const float* __restrict__ B, float* __restrict__ C,
    int M, int N, int K)
{
    __shared__ float As[BK][BM];
    __shared__ float Bs[BK][BN];
    int tid = threadIdx.x;          // 0..255
    int tx = tid & 15;
    int ty = tid >> 4;
    int m0 = blockIdx.y * BM;
    int n0 = blockIdx.x * BN;

    int arow = tid >> 1;            // 0..127
    int acol = (tid & 1) * 4;       // 0 or 4
    int brow = tid >> 5;            // 0..7
    int bcol = (tid & 31) * 4;      // 0..124

    float acc[8][8];
    #pragma unroll
    for (int i = 0; i < 8; i++)
        #pragma unroll
        for (int j = 0; j < 8; j++) acc[i][j] = 0.f;

    for (int k0 = 0; k0 < K; k0 += BK) {
        float4 av = make_float4(0.f, 0.f, 0.f, 0.f);
        if (m0 + arow < M)
            av = *(const float4*)(A + (size_t)(m0 + arow) * K + k0 + acol);
        As[acol + 0][arow] = av.x;
        As[acol + 1][arow] = av.y;
        As[acol + 2][arow] = av.z;
        As[acol + 3][arow] = av.w;

        float4 bv = *(const float4*)(B + (size_t)(k0 + brow) * N + n0 + bcol);
        *(float4*)&Bs[brow][bcol] = bv;
        __syncthreads();

        #pragma unroll
        for (int kk = 0; kk < BK; kk++) {
            float ra[8], rb[8];
            #pragma unroll
            for (int i = 0; i < 4; i++) {
                ra[i]     = As[kk][ty * 4 + i];
                ra[4 + i] = As[kk][64 + ty * 4 + i];
                rb[i]     = Bs[kk][tx * 4 + i];
                rb[4 + i] = Bs[kk][64 + tx * 4 + i];
            }
            #pragma unroll
            for (int i = 0; i < 8; i++)
                #pragma unroll
                for (int j = 0; j < 8; j++)
                    acc[i][j] = fmaf(ra[i], rb[j], acc[i][j]);
        }
        __syncthreads();
    }

    #pragma unroll
    for (int i = 0; i < 8; i++) {
        int r = m0 + ((i < 4) ? (ty * 4 + i) : (64 + ty * 4 + (i - 4)));
        if (r < M) {
            float rs = g_dis[r];
            float* cp = C + (size_t)r * N + n0;
            *(float4*)(cp + tx * 4) = make_float4(acc[i][0] * rs, acc[i][1] * rs,
                                                  acc[i][2] * rs, acc[i][3] * rs);
            *(float4*)(cp + 64 + tx * 4) = make_float4(acc[i][4] * rs, acc[i][5] * rs,
                                                       acc[i][6] * rs, acc[i][7] * rs);
        }
    }
}

// ---------------- gather aggregation + bias + relu ----------------
// hs rows are already scaled by dis[row]; out = relu(dis[n]*(self + sum_edges) + bias)
__global__ void agg_kernel(const float* __restrict__ hs, const float* __restrict__ bias,
                           float* __restrict__ out, int C)
{
    int n = blockIdx.x;
    int c = threadIdx.x;
    float dn = g_dis[n];
    int s0 = g_off[n], s1 = g_off[n + 1];
    float acc = hs[(size_t)n * C + c];   // self-loop term (already *dis[n])
    int j = s0;
    for (; j + 1 < s1; j += 2) {
        int sa = g_csr[j];
        int sb = g_csr[j + 1];
        float va = hs[(size_t)sa * C + c];
        float vb = hs[(size_t)sb * C + c];
        acc += va;
        acc += vb;
    }
    if (j < s1) acc += hs[(size_t)g_csr[j] * C + c];
    out[(size_t)n * C + c] = fmaxf(fmaf(acc, dn, bias[c]), 0.f);
}

// ---------------- graph-boundary detection (batch is sorted) ----------------
__global__ void bounds_kernel(const int* __restrict__ batch, int n) {
    int i = blockIdx.x * blockDim.x + threadIdx.x;
    if (i == 0) g_gs[N_GRAPHS] = n;
    if (i < n) {
        if (i == 0 || batch[i] != batch[i - 1]) g_gs[batch[i]] = i;
    }
}

// ---------------- global max pool per graph ----------------
__global__ void pool_kernel() {
    int g = blockIdx.x;
    int c = threadIdx.x;          // 0..127
    int a = g_gs[g], b = g_gs[g + 1];
    float m = -3.402823466e38f;
    int n = a;
    for (; n + 3 < b; n += 4) {
        float v0 = g_cx[(size_t)(n + 0) * HID2 + c];
        float v1 = g_cx[(size_t)(n + 1) * HID2 + c];
        float v2 = g_cx[(size_t)(n + 2) * HID2 + c];
        float v3 = g_cx[(size_t)(n + 3) * HID2 + c];
        m = fmaxf(m, fmaxf(fmaxf(v0, v1), fmaxf(v2, v3)));
    }
    for (; n < b; n++) m = fmaxf(m, g_cx[(size_t)n * HID2 + c]);
    g_px[g * HID2 + c] = m;
}

// ---------------- head: out[g][d] = px[g,:] @ Wm[:,d] + bm[d] ----------------
__global__ void head_kernel(const float* __restrict__ Wm, const float* __restrict__ bm,
                            float* __restrict__ out)
{
    int g = blockIdx.x;
    int d = threadIdx.x;          // 0..63
    float acc = bm[d];
    #pragma unroll 8
    for (int k = 0; k < HID2; k++)
        acc = fmaf(g_px[g * HID2 + k], Wm[k * N_DCS + d], acc);
    out[g * N_DCS + d] = acc;
}

// ---------------- launch ----------------
extern "C" void kernel_launch(void* const* d_in, const int* in_sizes, int n_in,
                              void* d_out, int out_size)
{
    const float* x     = (const float*)d_in[0];
    const int*   ei    = (const int*)  d_in[1];
    const int*   batch = (const int*)  d_in[2];
    const float* W1    = (const float*)d_in[3];
    // b1 = d_in[4]
    const float* W2    = (const float*)d_in[5];
    // b2 = d_in[6]
    const float* b1    = (const float*)d_in[4];
    const float* b2    = (const float*)d_in[6];
    const float* Wm    = (const float*)d_in[7];
    const float* bm    = (const float*)d_in[8];
    float* out = (float*)d_out;

    const int N = in_sizes[2];          // 50000
    const int E = in_sizes[1] / 2;      // 800000
    const int* src = ei;
    const int* dst = ei + E;

    float *h1, *bx, *h2, *cx;
    cudaGetSymbolAddress((void**)&h1, g_h1);
    cudaGetSymbolAddress((void**)&bx, g_bx);
    cudaGetSymbolAddress((void**)&h2, g_h2);
    cudaGetSymbolAddress((void**)&cx, g_cx);

    const int TB = 256;
    int gn = (N + TB - 1) / TB;
    int ge = (E + TB - 1) / TB;

    // --- graph structure (degree, dis, CSR by dst) ---
    zero_deg_kernel<<<gn, TB>>>(N);
    hist_kernel<<<ge, TB>>>(dst, E);
    dis_kernel<<<gn, TB>>>(N);
    scan_kernel<<<1, 1024>>>(N);
    copy_pos_kernel<<<gn, TB>>>(N);
    scatter_kernel<<<ge, TB>>>(src, dst, E);
    bounds_kernel<<<gn, TB>>>(batch, N);

    // --- layer 1: h1 = (x @ W1) * dis ; bx = relu(dis*(self+sum) + b1) ---
    {
        dim3 grid(HID / BN, (N + BM - 1) / BM);
        sgemm_scaled_kernel<<<grid, 256>>>(x, W1, h1, N, HID, IN_C);
    }
    agg_kernel<<<N, HID>>>(h1, b1, bx, HID);

    // --- layer 2: h2 = (bx @ W2) * dis ; cx = relu(dis*(self+sum) + b2) ---
    {
        dim3 grid(HID2 / BN, (N + BM - 1) / BM);
        sgemm_scaled_kernel<<<grid, 256>>>(bx, W2, h2, N, HID2, HID);
    }
    agg_kernel<<<N, HID2>>>(h2, b2, cx, HID2);

    // --- pool + head ---
    pool_kernel<<<N_GRAPHS, HID2>>>();
    head_kernel<<<N_GRAPHS, N_DCS>>>(Wm, bm, out);
}

// round 5
// speedup vs baseline: 1.0013x; 1.0013x over previous
#include <cuda_runtime.h>
#include <cstddef>

#define N_NODES 50000
#define N_EDGES 800000
#define N_GRAPHS 64
#define IN_C 256
#define HID 256
#define HID2 128
#define N_DCS 64

// ---------------- static device scratch (no allocations allowed) ----------------
__device__ float g_h1[(size_t)N_NODES * HID];    // (x@W1)*dis[row]
__device__ float g_bx[(size_t)N_NODES * HID];    // relu layer1 output
__device__ float g_h2[(size_t)N_NODES * HID2];   // (bx@W2)*dis[row]
__device__ float g_cx[(size_t)N_NODES * HID2];   // relu layer2 output
__device__ float g_dis[N_NODES];
__device__ int   g_deg[N_NODES];
__device__ int   g_off[N_NODES + 1];
__device__ int   g_pos[N_NODES];
__device__ int   g_csr[N_EDGES];
__device__ int   g_gs[N_GRAPHS + 1];
__device__ float g_px[N_GRAPHS * HID2];

// ---------------- graph preprocessing ----------------
__global__ void zero_deg_kernel(int n) {
    int i = blockIdx.x * blockDim.x + threadIdx.x;
    if (i < n) g_deg[i] = 0;
}

__global__ void hist_kernel(const int* __restrict__ dst, int e) {
    int i = blockIdx.x * blockDim.x + threadIdx.x;
    if (i < e) atomicAdd(&g_deg[dst[i]], 1);
}

__global__ void dis_kernel(int n) {
    int i = blockIdx.x * blockDim.x + threadIdx.x;
    if (i < n) g_dis[i] = rsqrtf((float)g_deg[i] + 1.0f);
}

// single-block exclusive scan over g_deg -> g_off  (n up to 50000)
__global__ void scan_kernel(int n) {
    __shared__ int sh[1024];
    __shared__ int carry_s;
    int tid = threadIdx.x;
    if (tid == 0) carry_s = 0;
    __syncthreads();
    for (int base = 0; base < n; base += 1024) {
        int i = base + tid;
        int v = (i < n) ? g_deg[i] : 0;
        sh[tid] = v;
        __syncthreads();
        #pragma unroll
        for (int s = 1; s < 1024; s <<= 1) {
            int t = (tid >= s) ? sh[tid - s] : 0;
            __syncthreads();
            sh[tid] += t;
            __syncthreads();
        }
        int incl = sh[tid];
        int c0 = carry_s;
        if (i < n) g_off[i] = c0 + incl - v;   // exclusive
        __syncthreads();
        if (tid == 0) carry_s = c0 + sh[1023];
        __syncthreads();
    }
    if (tid == 0) g_off[n] = carry_s;
}

__global__ void copy_pos_kernel(int n) {
    int i = blockIdx.x * blockDim.x + threadIdx.x;
    if (i < n) g_pos[i] = g_off[i];
}

__global__ void scatter_kernel(const int* __restrict__ src, const int* __restrict__ dst, int e) {
    int i = blockIdx.x * blockDim.x + threadIdx.x;
    if (i < e) {
        int d = dst[i];
        int p = atomicAdd(&g_pos[d], 1);
        g_csr[p] = src[i];
    }
}

// ---------------- SGEMM: C[r][c] = (A[r,:] @ B[:,c]) * g_dis[r] ----------------
// A: [M,K] row-major, B: [K,N] row-major. N % 128 == 0, K % 8 == 0, M guarded.
#define BM 128
#define BN 128
#define BK 8
__global__ __launch_bounds__(256) void sgemm_scaled_kernel(
    const float* __restrict__ A, const float* __restrict__ B, float* __restrict__ C,
    int M, int N, int K)
{
    __shared__ float As[BK][BM];
    __shared__ float Bs[BK][BN];
    int tid = threadIdx.x;          // 0..255
    int tx = tid & 15;
    int ty = tid >> 4;
    int m0 = blockIdx.y * BM;
    int n0 = blockIdx.x * BN;

    int arow = tid >> 1;            // 0..127
    int acol = (tid & 1) * 4;       // 0 or 4
    int brow = tid >> 5;            // 0..7
    int bcol = (tid & 31) * 4;      // 0..124

    float acc[8][8];
    #pragma unroll
    for (int i = 0; i < 8; i++)
        #pragma unroll
        for (int j = 0; j < 8; j++) acc[i][j] = 0.f;

    for (int k0 = 0; k0 < K; k0 += BK) {
        float4 av = make_float4(0.f, 0.f, 0.f, 0.f);
        if (m0 + arow < M)
            av = *(const float4*)(A + (size_t)(m0 + arow) * K + k0 + acol);
        As[acol + 0][arow] = av.x;
        As[acol + 1][arow] = av.y;
        As[acol + 2][arow] = av.z;
        As[acol + 3][arow] = av.w;

        float4 bv = *(const float4*)(B + (size_t)(k0 + brow) * N + n0 + bcol);
        *(float4*)&Bs[brow][bcol] = bv;
        __syncthreads();

        #pragma unroll
        for (int kk = 0; kk < BK; kk++) {
            float ra[8], rb[8];
            #pragma unroll
            for (int i = 0; i < 4; i++) {
                ra[i]     = As[kk][ty * 4 + i];
                ra[4 + i] = As[kk][64 + ty * 4 + i];
                rb[i]     = Bs[kk][tx * 4 + i];
                rb[4 + i] = Bs[kk][64 + tx * 4 + i];
            }
            #pragma unroll
            for (int i = 0; i < 8; i++)
                #pragma unroll
                for (int j = 0; j < 8; j++)
                    acc[i][j] = fmaf(ra[i], rb[j], acc[i][j]);
        }
        __syncthreads();
    }

    #pragma unroll
    for (int i = 0; i < 8; i++) {
        int r = m0 + ((i < 4) ? (ty * 4 + i) : (64 + ty * 4 + (i - 4)));
        if (r < M) {
            float rs = g_dis[r];
            float* cp = C + (size_t)r * N + n0;
            *(float4*)(cp + tx * 4) = make_float4(acc[i][0] * rs, acc[i][1] * rs,
                                                  acc[i][2] * rs, acc[i][3] * rs);
            *(float4*)(cp + 64 + tx * 4) = make_float4(acc[i][4] * rs, acc[i][5] * rs,
                                                       acc[i][6] * rs, acc[i][7] * rs);
        }
    }
}

// ---------------- gather aggregation + bias + relu ----------------
// hs rows are already scaled by dis[row]; out = relu(dis[n]*(self + sum_edges) + bias)
__global__ void agg_kernel(const float* __restrict__ hs, const float* __restrict__ bias,
                           float* __restrict__ out, int C)
{
    int n = blockIdx.x;
    int c = threadIdx.x;
    float dn = g_dis[n];
    int s0 = g_off[n], s1 = g_off[n + 1];
    float acc = hs[(size_t)n * C + c];   // self-loop term (already *dis[n])
    int j = s0;
    for (; j + 1 < s1; j += 2) {
        int sa = g_csr[j];
        int sb = g_csr[j + 1];
        float va = hs[(size_t)sa * C + c];
        float vb = hs[(size_t)sb * C + c];
        acc += va;
        acc += vb;
    }
    if (j < s1) acc += hs[(size_t)g_csr[j] * C + c];
    out[(size_t)n * C + c] = fmaxf(fmaf(acc, dn, bias[c]), 0.f);
}

// ---------------- graph-boundary detection (batch is sorted) ----------------
__global__ void bounds_kernel(const int* __restrict__ batch, int n) {
    int i = blockIdx.x * blockDim.x + threadIdx.x;
    if (i == 0) g_gs[N_GRAPHS] = n;
    if (i < n) {
        if (i == 0 || batch[i] != batch[i - 1]) g_gs[batch[i]] = i;
    }
}

// ---------------- global max pool per graph ----------------
__global__ void pool_kernel() {
    int g = blockIdx.x;
    int c = threadIdx.x;          // 0..127
    int a = g_gs[g], b = g_gs[g + 1];
    float m = -3.402823466e38f;
    int n = a;
    for (; n + 3 < b; n += 4) {
        float v0 = g_cx[(size_t)(n + 0) * HID2 + c];
        float v1 = g_cx[(size_t)(n + 1) * HID2 + c];
        float v2 = g_cx[(size_t)(n + 2) * HID2 + c];
        float v3 = g_cx[(size_t)(n + 3) * HID2 + c];
        m = fmaxf(m, fmaxf(fmaxf(v0, v1), fmaxf(v2, v3)));
    }
    for (; n < b; n++) m = fmaxf(m, g_cx[(size_t)n * HID2 + c]);
    g_px[g * HID2 + c] = m;
}

// ---------------- head: out[g][d] = px[g,:] @ Wm[:,d] + bm[d] ----------------
__global__ void head_kernel(const float* __restrict__ Wm, const float* __restrict__ bm,
                            float* __restrict__ out)
{
    int g = blockIdx.x;
    int d = threadIdx.x;          // 0..63
    float acc = bm[d];
    #pragma unroll 8
    for (int k = 0; k < HID2; k++)
        acc = fmaf(g_px[g * HID2 + k], Wm[k * N_DCS + d], acc);
    out[g * N_DCS + d] = acc;
}

// ---------------- launch ----------------
extern "C" void kernel_launch(void* const* d_in, const int* in_sizes, int n_in,
                              void* d_out, int out_size)
{
    const float* x     = (const float*)d_in[0];
    const int*   ei    = (const int*)  d_in[1];
    const int*   batch = (const int*)  d_in[2];
    const float* W1    = (const float*)d_in[3];
    // b1 = d_in[4]
    const float* W2    = (const float*)d_in[5];
    // b2 = d_in[6]
    const float* b1    = (const float*)d_in[4];
    const float* b2    = (const float*)d_in[6];
    const float* Wm    = (const float*)d_in[7];
    const float* bm    = (const float*)d_in[8];
    float* out = (float*)d_out;

    const int N = in_sizes[2];          // 50000
    const int E = in_sizes[1] / 2;      // 800000
    const int* src = ei;
    const int* dst = ei + E;

    float *h1, *bx, *h2, *cx;
    cudaGetSymbolAddress((void**)&h1, g_h1);
    cudaGetSymbolAddress((void**)&bx, g_bx);
    cudaGetSymbolAddress((void**)&h2, g_h2);
    cudaGetSymbolAddress((void**)&cx, g_cx);

    const int TB = 256;
    int gn = (N + TB - 1) / TB;
    int ge = (E + TB - 1) / TB;

    // --- graph structure (degree, dis, CSR by dst) ---
    zero_deg_kernel<<<gn, TB>>>(N);
    hist_kernel<<<ge, TB>>>(dst, E);
    dis_kernel<<<gn, TB>>>(N);
    scan_kernel<<<1, 1024>>>(N);
    copy_pos_kernel<<<gn, TB>>>(N);
    scatter_kernel<<<ge, TB>>>(src, dst, E);
    bounds_kernel<<<gn, TB>>>(batch, N);

    // --- layer 1: h1 = (x @ W1) * dis ; bx = relu(dis*(self+sum) + b1) ---
    {
        dim3 grid(HID / BN, (N + BM - 1) / BM);
        sgemm_scaled_kernel<<<grid, 256>>>(x, W1, h1, N, HID, IN_C);
    }
    agg_kernel<<<N, HID>>>(h1, b1, bx, HID);

    // --- layer 2: h2 = (bx @ W2) * dis ; cx = relu(dis*(self+sum) + b2) ---
    {
        dim3 grid(HID2 / BN, (N + BM - 1) / BM);
        sgemm_scaled_kernel<<<grid, 256>>>(bx, W2, h2, N, HID2, HID);
    }
    agg_kernel<<<N, HID2>>>(h2, b2, cx, HID2);

    // --- pool + head ---
    pool_kernel<<<N_GRAPHS, HID2>>>();
    head_kernel<<<N_GRAPHS, N_DCS>>>(Wm, bm, out);
}

// round 7
// speedup vs baseline: 1.4292x; 1.4273x over previous
#include <cuda_runtime.h>
#include <cuda_bf16.h>
#include <cstdint>
#include <cstddef>

#define N_NODES 50000
#define N_EDGES 800000
#define N_GRAPHS 64
#define IN_C 256
#define HID 256
#define HID2 128
#define N_DCS 64

// ---------------- static device scratch (no allocations allowed) ----------------
__device__ float g_h1[(size_t)N_NODES * HID];            // (x@W1)*dis[row] fp32
__device__ float g_h2[(size_t)N_NODES * HID2];           // (bx@W2)*dis[row] fp32
__device__ float g_cx[(size_t)N_NODES * HID2];           // relu layer2 output
__device__ __nv_bfloat16 g_xh[(size_t)N_NODES * IN_C];   // x split hi
__device__ __nv_bfloat16 g_xl[(size_t)N_NODES * IN_C];   // x split lo
__device__ __nv_bfloat16 g_bxh[(size_t)N_NODES * HID];   // relu layer1 split hi
__device__ __nv_bfloat16 g_bxl[(size_t)N_NODES * HID];   // relu layer1 split lo
__device__ __nv_bfloat16 g_w1h[HID * IN_C];              // W1^T packed [N][K]
__device__ __nv_bfloat16 g_w1l[HID * IN_C];
__device__ __nv_bfloat16 g_w2h[HID2 * HID];
__device__ __nv_bfloat16 g_w2l[HID2 * HID];
__device__ float g_dis[N_NODES];
__device__ int   g_deg[N_NODES];
__device__ int   g_off[N_NODES + 1];
__device__ int   g_pos[N_NODES];
__device__ int   g_csr[N_EDGES];
__device__ int   g_bsum[64];
__device__ int   g_boff[64];
__device__ int   g_gs[N_GRAPHS + 1];
__device__ float g_px[N_GRAPHS * HID2];

// ---------------- helpers ----------------
__device__ __forceinline__ uint32_t smem_u32(const void* p) {
    uint32_t a;
    asm("{ .reg .u64 t; cvta.to.shared.u64 t, %1; cvt.u32.u64 %0, t; }" : "=r"(a) : "l"(p));
    return a;
}
__device__ __forceinline__ uint32_t lds32(uint32_t addr) {
    uint32_t v;
    asm volatile("ld.shared.b32 %0, [%1];" : "=r"(v) : "r"(addr));
    return v;
}
#define SWZ(o) ((uint32_t)(o) ^ ((((uint32_t)(o)) >> 3) & 0x70u))

// bf16 mma: D(4xf32) += A(4x.b32 bf16x2) * B(2x.b32 bf16x2)
#define MMA_BF16(d, a, b) \
    asm volatile("mma.sync.aligned.m16n8k16.row.col.f32.bf16.bf16.f32 " \
        "{%0,%1,%2,%3}, {%4,%5,%6,%7}, {%8,%9}, {%0,%1,%2,%3};" \
        : "+f"((d)[0]), "+f"((d)[1]), "+f"((d)[2]), "+f"((d)[3]) \
        : "r"((a)[0]), "r"((a)[1]), "r"((a)[2]), "r"((a)[3]), \
          "r"((b)[0]), "r"((b)[1]))

// ---------------- graph preprocessing ----------------
__global__ void zero_deg_kernel(int n) {
    int i = blockIdx.x * blockDim.x + threadIdx.x;
    if (i < n) g_deg[i] = 0;
}
__global__ void hist_kernel(const int* __restrict__ dst, int e) {
    int i = blockIdx.x * blockDim.x + threadIdx.x;
    if (i < e) atomicAdd(&g_deg[dst[i]], 1);
}
__global__ void dis_kernel(int n) {
    int i = blockIdx.x * blockDim.x + threadIdx.x;
    if (i < n) g_dis[i] = rsqrtf((float)g_deg[i] + 1.0f);
}
// stage 1: per-block (1024 elems) local exclusive scan + block sum
__global__ void scan_block_kernel(int n) {
    __shared__ int sh[1024];
    int tid = threadIdx.x;
    int i = blockIdx.x * 1024 + tid;
    int v = (i < n) ? g_deg[i] : 0;
    sh[tid] = v;
    __syncthreads();
    #pragma unroll
    for (int s = 1; s < 1024; s <<= 1) {
        int t = (tid >= s) ? sh[tid - s] : 0;
        __syncthreads();
        sh[tid] += t;
        __syncthreads();
    }
    if (i < n) g_off[i] = sh[tid] - v;     // local exclusive
    if (tid == 1023) g_bsum[blockIdx.x] = sh[1023];
}
// stage 2: scan block sums (nb <= 64), write total to g_off[n]
__global__ void scan_sums_kernel(int nb, int n) {
    __shared__ int sh[64];
    int tid = threadIdx.x;            // 64 threads
    int v = (tid < nb) ? g_bsum[tid] : 0;
    sh[tid] = v;
    __syncthreads();
    #pragma unroll
    for (int s = 1; s < 64; s <<= 1) {
        int t = (tid >= s) ? sh[tid - s] : 0;
        __syncthreads();
        sh[tid] += t;
        __syncthreads();
    }
    if (tid < nb) g_boff[tid] = sh[tid] - v;  // exclusive
    if (tid == nb - 1) g_off[n] = sh[tid];    // total edges
}
// stage 3: add block offsets; also seed g_pos
__global__ void scan_add_kernel(int n) {
    int i = blockIdx.x * blockDim.x + threadIdx.x;
    if (i < n) {
        int o = g_off[i] + g_boff[i >> 10];
        g_off[i] = o;
        g_pos[i] = o;
    }
}
__global__ void scatter_kernel(const int* __restrict__ src, const int* __restrict__ dst, int e) {
    int i = blockIdx.x * blockDim.x + threadIdx.x;
    if (i < e) {
        int d = dst[i];
        int p = atomicAdd(&g_pos[d], 1);
        g_csr[p] = src[i];
    }
}
__global__ void bounds_kernel(const int* __restrict__ batch, int n) {
    int i = blockIdx.x * blockDim.x + threadIdx.x;
    if (i == 0) g_gs[N_GRAPHS] = n;
    if (i < n) {
        if (i == 0 || batch[i] != batch[i - 1]) g_gs[batch[i]] = i;
    }
}

// ---------------- fp32 -> bf16 hi/lo split (for MMA inputs) ----------------
__global__ void split_x_kernel(const float* __restrict__ src,
                               __nv_bfloat16* __restrict__ hi,
                               __nv_bfloat16* __restrict__ lo, int total4) {
    int i = blockIdx.x * blockDim.x + threadIdx.x;
    if (i >= total4) return;
    float4 v = ((const float4*)src)[i];
    __nv_bfloat16 h0 = __float2bfloat16(v.x), h1 = __float2bfloat16(v.y);
    __nv_bfloat16 h2 = __float2bfloat16(v.z), h3 = __float2bfloat16(v.w);
    __nv_bfloat16 l0 = __float2bfloat16(v.x - __bfloat162float(h0));
    __nv_bfloat16 l1 = __float2bfloat16(v.y - __bfloat162float(h1));
    __nv_bfloat16 l2 = __float2bfloat16(v.z - __bfloat162float(h2));
    __nv_bfloat16 l3 = __float2bfloat16(v.w - __bfloat162float(h3));
    __nv_bfloat162* hp = (__nv_bfloat162*)hi;
    __nv_bfloat162* lp = (__nv_bfloat162*)lo;
    hp[i * 2]     = __halves2bfloat162(h0, h1);
    hp[i * 2 + 1] = __halves2bfloat162(h2, h3);
    lp[i * 2]     = __halves2bfloat162(l0, l1);
    lp[i * 2 + 1] = __halves2bfloat162(l2, l3);
}

// pack W [K=256, Ncols] row-major -> transposed bf16 hi/lo [Ncols][256]
__global__ void pack_w_kernel(const float* __restrict__ W,
                              __nv_bfloat16* __restrict__ hi,
                              __nv_bfloat16* __restrict__ lo, int Ncols) {
    int n = blockIdx.x;
    int k = threadIdx.x;        // 256
    float v = W[(size_t)k * Ncols + n];
    __nv_bfloat16 h = __float2bfloat16(v);
    __nv_bfloat16 l = __float2bfloat16(v - __bfloat162float(h));
    hi[(size_t)n * 256 + k] = h;
    lo[(size_t)n * 256 + k] = l;
}

// ================ mma.sync bf16x3 GEMM: C[r][c] = (A[r,:]@B[c,:]^T) * g_dis[r] ================
// A = Ah+Al (bf16 split, [M,256] row-major), B = Bh+Bl ([NTOT,256] row-major, pre-transposed W)
// CTA tile 128x128, K=256 chunked by 64 (SW128-swizzled 128B SMEM rows).
// 8 warps in 2x4 arrangement; warp tile 64x32 via m16n8k16 HMMA.
template <int NTOT>
__global__ __launch_bounds__(256, 2) void mma_gemm_kernel(
    const __nv_bfloat16* __restrict__ Ah, const __nv_bfloat16* __restrict__ Al,
    const __nv_bfloat16* __restrict__ Bh, const __nv_bfloat16* __restrict__ Bl,
    float* __restrict__ C, int M)
{
    constexpr int K = 256;
    constexpr int TILE = 128 * 128;               // bytes per SMEM tile (128 rows x 64 bf16)
    extern __shared__ char sm[];
    uint32_t sb = smem_u32(sm);
    const uint32_t sAh = sb, sAl = sb + TILE, sBh = sb + 2 * TILE, sBl = sb + 3 * TILE;

    const int tid = threadIdx.x;
    const int wid = tid >> 5;
    const int lane = tid & 31;
    const int g = lane >> 2;            // groupID 0..7
    const int t = lane & 3;             // thread-in-group
    const int wm = wid >> 2;            // 0..1
    const int wn = wid & 3;             // 0..3
    const int m0 = blockIdx.x * 128;
    const int n0 = blockIdx.y * 128;

    float acc[4][4][4];
    #pragma unroll
    for (int i = 0; i < 4; i++)
        #pragma unroll
        for (int j = 0; j < 4; j++)
            #pragma unroll
            for (int q = 0; q < 4; q++) acc[i][j][q] = 0.f;

    // precomputed A/B row byte-bases within tile
    uint32_t arow[4];   // A row (upper half adds +8*128)
    uint32_t brow[4];
    #pragma unroll
    for (int mi = 0; mi < 4; mi++) arow[mi] = (uint32_t)(wm * 64 + mi * 16 + g) * 128;
    #pragma unroll
    for (int ni = 0; ni < 4; ni++) brow[ni] = (uint32_t)(wn * 32 + ni * 8 + g) * 128;

    for (int c = 0; c < 4; c++) {
        const int k0 = c * 64;
        // cooperative load: 128 rows x 4 tiles, 8 x 16B per row
        #pragma unroll
        for (int v = tid; v < 1024; v += 256) {
            int row = v >> 3, u = v & 7;
            uint32_t so = SWZ((uint32_t)(row * 128 + u * 16));
            uint4 hv = make_uint4(0, 0, 0, 0), lv = make_uint4(0, 0, 0, 0);
            if (m0 + row < M) {
                size_t gi = (size_t)(m0 + row) * K + k0 + u * 8;
                hv = *(const uint4*)(Ah + gi);
                lv = *(const uint4*)(Al + gi);
            }
            *(uint4*)(sm + so)        = hv;
            *(uint4*)(sm + TILE + so) = lv;
            size_t gb = (size_t)(n0 + row) * K + k0 + u * 8;
            *(uint4*)(sm + 2 * TILE + so) = *(const uint4*)(Bh + gb);
            *(uint4*)(sm + 3 * TILE + so) = *(const uint4*)(Bl + gb);
        }
        __syncthreads();

        #pragma unroll
        for (int ks = 0; ks < 4; ks++) {
            const uint32_t kb0 = (uint32_t)(ks * 32 + t * 4);
            const uint32_t kb1 = kb0 + 16;

            uint32_t afr[4][4];
            // A hi fragments
            #pragma unroll
            for (int mi = 0; mi < 4; mi++) {
                afr[mi][0] = lds32(sAh + SWZ(arow[mi] + kb0));
                afr[mi][1] = lds32(sAh + SWZ(arow[mi] + 1024 + kb0));  // +8 rows
                afr[mi][2] = lds32(sAh + SWZ(arow[mi] + kb1));
                afr[mi][3] = lds32(sAh + SWZ(arow[mi] + 1024 + kb1));
            }
            uint32_t bfr[4][2];
            // B hi fragments : Ah*Bh
            #pragma unroll
            for (int ni = 0; ni < 4; ni++) {
                bfr[ni][0] = lds32(sBh + SWZ(brow[ni] + kb0));
                bfr[ni][1] = lds32(sBh + SWZ(brow[ni] + kb1));
            }
            #pragma unroll
            for (int mi = 0; mi < 4; mi++)
                #pragma unroll
                for (int ni = 0; ni < 4; ni++) MMA_BF16(acc[mi][ni], afr[mi], bfr[ni]);
            // B lo fragments : Ah*Bl
            #pragma unroll
            for (int ni = 0; ni < 4; ni++) {
                bfr[ni][0] = lds32(sBl + SWZ(brow[ni] + kb0));
                bfr[ni][1] = lds32(sBl + SWZ(brow[ni] + kb1));
            }
            #pragma unroll
            for (int mi = 0; mi < 4; mi++)
                #pragma unroll
                for (int ni = 0; ni < 4; ni++) MMA_BF16(acc[mi][ni], afr[mi], bfr[ni]);
            // A lo fragments, B hi again : Al*Bh
            #pragma unroll
            for (int mi = 0; mi < 4; mi++) {
                afr[mi][0] = lds32(sAl + SWZ(arow[mi] + kb0));
                afr[mi][1] = lds32(sAl + SWZ(arow[mi] + 1024 + kb0));
                afr[mi][2] = lds32(sAl + SWZ(arow[mi] + kb1));
                afr[mi][3] = lds32(sAl + SWZ(arow[mi] + 1024 + kb1));
            }
            #pragma unroll
            for (int ni = 0; ni < 4; ni++) {
                bfr[ni][0] = lds32(sBh + SWZ(brow[ni] + kb0));
                bfr[ni][1] = lds32(sBh + SWZ(brow[ni] + kb1));
            }
            #pragma unroll
            for (int mi = 0; mi < 4; mi++)
                #pragma unroll
                for (int ni = 0; ni < 4; ni++) MMA_BF16(acc[mi][ni], afr[mi], bfr[ni]);
        }
        __syncthreads();
    }

    // epilogue: scale by dis[row] and store
    #pragma unroll
    for (int mi = 0; mi < 4; mi++) {
        int r0 = m0 + wm * 64 + mi * 16 + g;
        int r1 = r0 + 8;
        float s0 = (r0 < M) ? g_dis[r0] : 0.f;
        float s1 = (r1 < M) ? g_dis[r1] : 0.f;
        #pragma unroll
        for (int ni = 0; ni < 4; ni++) {
            int col = n0 + wn * 32 + ni * 8 + t * 2;
            if (r0 < M)
                *(float2*)(C + (size_t)r0 * NTOT + col) =
                    make_float2(acc[mi][ni][0] * s0, acc[mi][ni][1] * s0);
            if (r1 < M)
                *(float2*)(C + (size_t)r1 * NTOT + col) =
                    make_float2(acc[mi][ni][2] * s1, acc[mi][ni][3] * s1);
        }
    }
}

// ---------------- gather aggregation (layer 1): bias+relu -> bf16 hi/lo split ----------------
__global__ void agg_split_kernel(const float* __restrict__ hs, const float* __restrict__ bias,
                                 __nv_bfloat16* __restrict__ oh, __nv_bfloat16* __restrict__ ol)
{
    const int C = HID;
    int n = blockIdx.x;
    int c = threadIdx.x;
    float dn = g_dis[n];
    int s0 = g_off[n], s1 = g_off[n + 1];
    float acc = hs[(size_t)n * C + c];      // self-loop (already *dis[n])
    int j = s0;
    for (; j + 1 < s1; j += 2) {
        int sa = g_csr[j];
        int sb = g_csr[j + 1];
        acc += hs[(size_t)sa * C + c];
        acc += hs[(size_t)sb * C + c];
    }
    if (j < s1) acc += hs[(size_t)g_csr[j] * C + c];
    float v = fmaxf(fmaf(acc, dn, bias[c]), 0.f);
    __nv_bfloat16 h = __float2bfloat16(v);
    __nv_bfloat16 l = __float2bfloat16(v - __bfloat162float(h));
    oh[(size_t)n * C + c] = h;
    ol[(size_t)n * C + c] = l;
}

// ---------------- gather aggregation (layer 2): bias+relu -> fp32 ----------------
__global__ void agg2_kernel(const float* __restrict__ hs, const float* __restrict__ bias,
                            float* __restrict__ out)
{
    const int C = HID2;
    int n = blockIdx.x;
    int c = threadIdx.x;
    float dn = g_dis[n];
    int s0 = g_off[n], s1 = g_off[n + 1];
    float acc = hs[(size_t)n * C + c];
    int j = s0;
    for (; j + 1 < s1; j += 2) {
        int sa = g_csr[j];
        int sb = g_csr[j + 1];
        acc += hs[(size_t)sa * C + c];
        acc += hs[(size_t)sb * C + c];
    }
    if (j < s1) acc += hs[(size_t)g_csr[j] * C + c];
    out[(size_t)n * C + c] = fmaxf(fmaf(acc, dn, bias[c]), 0.f);
}

// ---------------- global max pool per graph ----------------
__global__ void pool_kernel() {
    int g = blockIdx.x;
    int c = threadIdx.x;          // 0..127
    int a = g_gs[g], b = g_gs[g + 1];
    float m = -3.402823466e38f;
    int n = a;
    for (; n + 3 < b; n += 4) {
        float v0 = g_cx[(size_t)(n + 0) * HID2 + c];
        float v1 = g_cx[(size_t)(n + 1) * HID2 + c];
        float v2 = g_cx[(size_t)(n + 2) * HID2 + c];
        float v3 = g_cx[(size_t)(n + 3) * HID2 + c];
        m = fmaxf(m, fmaxf(fmaxf(v0, v1), fmaxf(v2, v3)));
    }
    for (; n < b; n++) m = fmaxf(m, g_cx[(size_t)n * HID2 + c]);
    g_px[g * HID2 + c] = m;
}

// ---------------- head ----------------
__global__ void head_kernel(const float* __restrict__ Wm, const float* __restrict__ bm,
                            float* __restrict__ out)
{
    int g = blockIdx.x;
    int d = threadIdx.x;          // 0..63
    float acc = bm[d];
    #pragma unroll 8
    for (int k = 0; k < HID2; k++)
        acc = fmaf(g_px[g * HID2 + k], Wm[k * N_DCS + d], acc);
    out[g * N_DCS + d] = acc;
}

// ---------------- launch ----------------
extern "C" void kernel_launch(void* const* d_in, const int* in_sizes, int n_in,
                              void* d_out, int out_size)
{
    const float* x     = (const float*)d_in[0];
    const int*   ei    = (const int*)  d_in[1];
    const int*   batch = (const int*)  d_in[2];
    const float* W1    = (const float*)d_in[3];
    const float* b1    = (const float*)d_in[4];
    const float* W2    = (const float*)d_in[5];
    const float* b2    = (const float*)d_in[6];
    const float* Wm    = (const float*)d_in[7];
    const float* bm    = (const float*)d_in[8];
    float* out = (float*)d_out;

    const int N = in_sizes[2];          // 50000
    const int E = in_sizes[1] / 2;      // 800000
    const int* src = ei;
    const int* dst = ei + E;

    float *h1, *h2;
    __nv_bfloat16 *xh, *xl, *bxh, *bxl, *w1h, *w1l, *w2h, *w2l;
    cudaGetSymbolAddress((void**)&h1, g_h1);
    cudaGetSymbolAddress((void**)&h2, g_h2);
    cudaGetSymbolAddress((void**)&xh, g_xh);
    cudaGetSymbolAddress((void**)&xl, g_xl);
    cudaGetSymbolAddress((void**)&bxh, g_bxh);
    cudaGetSymbolAddress((void**)&bxl, g_bxl);
    cudaGetSymbolAddress((void**)&w1h, g_w1h);
    cudaGetSymbolAddress((void**)&w1l, g_w1l);
    cudaGetSymbolAddress((void**)&w2h, g_w2h);
    cudaGetSymbolAddress((void**)&w2l, g_w2l);
    float* cx;
    cudaGetSymbolAddress((void**)&cx, g_cx);

    const int TB = 256;
    int gn = (N + TB - 1) / TB;
    int ge = (E + TB - 1) / TB;
    int nb = (N + 1023) / 1024;         // 49 scan blocks

    // --- graph structure ---
    zero_deg_kernel<<<gn, TB>>>(N);
    hist_kernel<<<ge, TB>>>(dst, E);
    dis_kernel<<<gn, TB>>>(N);
    scan_block_kernel<<<nb, 1024>>>(N);
    scan_sums_kernel<<<1, 64>>>(nb, N);
    scan_add_kernel<<<gn, TB>>>(N);
    scatter_kernel<<<ge, TB>>>(src, dst, E);
    bounds_kernel<<<gn, TB>>>(batch, N);

    // --- input conversions ---
    {
        int total4 = N * IN_C / 4;
        split_x_kernel<<<(total4 + TB - 1) / TB, TB>>>(x, xh, xl, total4);
    }
    pack_w_kernel<<<HID, 256>>>(W1, w1h, w1l, HID);
    pack_w_kernel<<<HID2, 256>>>(W2, w2h, w2l, HID2);

    const int SMEM = 4 * 128 * 128;     // 65536 bytes
    int mtiles = (N + 127) / 128;

    // --- layer 1 GEMM (HMMA bf16x3): h1 = (x@W1)*dis ---
    {
        cudaFuncSetAttribute(mma_gemm_kernel<HID>,
                             cudaFuncAttributeMaxDynamicSharedMemorySize, SMEM);
        dim3 grid(mtiles, HID / 128);
        mma_gemm_kernel<HID><<<grid, 256, SMEM>>>(xh, xl, w1h, w1l, h1, N);
    }
    agg_split_kernel<<<N, HID>>>(h1, b1, bxh, bxl);

    // --- layer 2 GEMM: h2 = (bx@W2)*dis ---
    {
        cudaFuncSetAttribute(mma_gemm_kernel<HID2>,
                             cudaFuncAttributeMaxDynamicSharedMemorySize, SMEM);
        dim3 grid(mtiles, HID2 / 128);
        mma_gemm_kernel<HID2><<<grid, 256, SMEM>>>(bxh, bxl, w2h, w2l, h2, N);
    }
    agg2_kernel<<<N, HID2>>>(h2, b2, cx);

    // --- pool + head ---
    pool_kernel<<<N_GRAPHS, HID2>>>();
    head_kernel<<<N_GRAPHS, N_DCS>>>(Wm, bm, out);
}

// round 8
// speedup vs baseline: 1.8406x; 1.2878x over previous
#include <cuda_runtime.h>
#include <cuda_bf16.h>
#include <cstdint>
#include <cstddef>

#define N_NODES 50000
#define N_EDGES 800000
#define N_GRAPHS 64
#define IN_C 256
#define HID 256
#define HID2 128
#define N_DCS 64

// ---------------- static device scratch (no allocations allowed) ----------------
__device__ float g_h1[(size_t)N_NODES * HID];            // (x@W1)*dis[row] fp32
__device__ float g_bx[(size_t)N_NODES * HID];            // relu layer1 output fp32
__device__ float g_h2[(size_t)N_NODES * HID2];           // (bx@W2)*dis[row] fp32
__device__ float g_cx[(size_t)N_NODES * HID2];           // relu layer2 output
__device__ __nv_bfloat16 g_w1h[HID * IN_C];              // W1^T packed [N][K] hi
__device__ __nv_bfloat16 g_w1l[HID * IN_C];
__device__ __nv_bfloat16 g_w2h[HID2 * HID];
__device__ __nv_bfloat16 g_w2l[HID2 * HID];
__device__ float g_dis[N_NODES];
__device__ int   g_deg[N_NODES];
__device__ int   g_off[N_NODES + 1];
__device__ int   g_pos[N_NODES];
__device__ int   g_csr[N_EDGES];
__device__ int   g_bsum[64];
__device__ int   g_boff[64];
__device__ int   g_gs[N_GRAPHS + 1];
__device__ float g_px[N_GRAPHS * HID2];

// ---------------- helpers ----------------
__device__ __forceinline__ uint32_t smem_u32(const void* p) {
    uint32_t a;
    asm("{ .reg .u64 t; cvta.to.shared.u64 t, %1; cvt.u32.u64 %0, t; }" : "=r"(a) : "l"(p));
    return a;
}
__device__ __forceinline__ uint32_t lds32(uint32_t addr) {
    uint32_t v;
    asm volatile("ld.shared.b32 %0, [%1];" : "=r"(v) : "r"(addr));
    return v;
}
#define SWZ(o) ((uint32_t)(o) ^ ((((uint32_t)(o)) >> 3) & 0x70u))

// bf16 mma: D(4xf32) += A(4x.b32 bf16x2) * B(2x.b32 bf16x2)
#define MMA_BF16(d, a, b) \
    asm volatile("mma.sync.aligned.m16n8k16.row.col.f32.bf16.bf16.f32 " \
        "{%0,%1,%2,%3}, {%4,%5,%6,%7}, {%8,%9}, {%0,%1,%2,%3};" \
        : "+f"((d)[0]), "+f"((d)[1]), "+f"((d)[2]), "+f"((d)[3]) \
        : "r"((a)[0]), "r"((a)[1]), "r"((a)[2]), "r"((a)[3]), \
          "r"((b)[0]), "r"((b)[1]))

// split two fp32 -> packed bf16x2 hi and lo words
__device__ __forceinline__ void split2(float f0, float f1, uint32_t& h, uint32_t& l) {
    __nv_bfloat162 hp = __floats2bfloat162_rn(f0, f1);
    float2 hf = __bfloat1622float2(hp);
    __nv_bfloat162 lp = __floats2bfloat162_rn(f0 - hf.x, f1 - hf.y);
    h = *reinterpret_cast<uint32_t*>(&hp);
    l = *reinterpret_cast<uint32_t*>(&lp);
}

// ---------------- fused prep: zero g_deg + pack W1/W2 transposed bf16 hi/lo ----------------
#define ZB ((N_NODES + 255) / 256)
__global__ void prep_kernel(const float* __restrict__ W1, const float* __restrict__ W2) {
    int b = blockIdx.x;
    int t = threadIdx.x;                 // 256
    if (b < ZB) {
        int i = b * 256 + t;
        if (i < N_NODES) g_deg[i] = 0;
    } else if (b < ZB + HID) {
        int n = b - ZB;                  // W1 column
        float v = W1[(size_t)t * HID + n];
        __nv_bfloat16 h = __float2bfloat16(v);
        g_w1h[(size_t)n * 256 + t] = h;
        g_w1l[(size_t)n * 256 + t] = __float2bfloat16(v - __bfloat162float(h));
    } else {
        int n = b - ZB - HID;            // W2 column
        float v = W2[(size_t)t * HID2 + n];
        __nv_bfloat16 h = __float2bfloat16(v);
        g_w2h[(size_t)n * 256 + t] = h;
        g_w2l[(size_t)n * 256 + t] = __float2bfloat16(v - __bfloat162float(h));
    }
}

__global__ void hist_kernel(const int* __restrict__ dst, int e) {
    int i = blockIdx.x * blockDim.x + threadIdx.x;
    if (i < e) atomicAdd(&g_deg[dst[i]], 1);
}
__global__ void dis_kernel(int n) {
    int i = blockIdx.x * blockDim.x + threadIdx.x;
    if (i < n) g_dis[i] = rsqrtf((float)g_deg[i] + 1.0f);
}
// stage 1: per-block (1024 elems) local exclusive scan + block sum
__global__ void scan_block_kernel(int n) {
    __shared__ int sh[1024];
    int tid = threadIdx.x;
    int i = blockIdx.x * 1024 + tid;
    int v = (i < n) ? g_deg[i] : 0;
    sh[tid] = v;
    __syncthreads();
    #pragma unroll
    for (int s = 1; s < 1024; s <<= 1) {
        int t = (tid >= s) ? sh[tid - s] : 0;
        __syncthreads();
        sh[tid] += t;
        __syncthreads();
    }
    if (i < n) g_off[i] = sh[tid] - v;     // local exclusive
    if (tid == 1023) g_bsum[blockIdx.x] = sh[1023];
}
__global__ void scan_sums_kernel(int nb, int n) {
    __shared__ int sh[64];
    int tid = threadIdx.x;            // 64 threads
    int v = (tid < nb) ? g_bsum[tid] : 0;
    sh[tid] = v;
    __syncthreads();
    #pragma unroll
    for (int s = 1; s < 64; s <<= 1) {
        int t = (tid >= s) ? sh[tid - s] : 0;
        __syncthreads();
        sh[tid] += t;
        __syncthreads();
    }
    if (tid < nb) g_boff[tid] = sh[tid] - v;  // exclusive
    if (tid == nb - 1) g_off[n] = sh[tid];    // total
}
__global__ void scan_add_kernel(int n) {
    int i = blockIdx.x * blockDim.x + threadIdx.x;
    if (i < n) {
        int o = g_off[i] + g_boff[i >> 10];
        g_off[i] = o;
        g_pos[i] = o;
    }
}
__global__ void scatter_kernel(const int* __restrict__ src, const int* __restrict__ dst, int e) {
    int i = blockIdx.x * blockDim.x + threadIdx.x;
    if (i < e) {
        int d = dst[i];
        int p = atomicAdd(&g_pos[d], 1);
        g_csr[p] = src[i];
    }
}
__global__ void bounds_kernel(const int* __restrict__ batch, int n) {
    int i = blockIdx.x * blockDim.x + threadIdx.x;
    if (i == 0) g_gs[N_GRAPHS] = n;
    if (i < n) {
        if (i == 0 || batch[i] != batch[i - 1]) g_gs[batch[i]] = i;
    }
}

// ================ mma.sync bf16x3 GEMM: C[r][c] = (A[r,:]@B[c,:]^T) * g_dis[r] ================
// A fp32 [M,256] row-major (split to bf16 hi/lo in-kernel).
// B = Bh+Bl bf16 ([NTOT,256] row-major, pre-transposed weights).
// CTA tile 128x128, K=256 chunked by 64 (SW128-swizzled 128B SMEM rows).
// 8 warps in 2x4; warp tile 64x32 via m16n8k16 HMMA; 3 MMA passes (AhBh, AhBl, AlBh).
template <int NTOT>
__global__ __launch_bounds__(256, 2) void mma_gemm_kernel(
    const float* __restrict__ A,
    const __nv_bfloat16* __restrict__ Bh, const __nv_bfloat16* __restrict__ Bl,
    float* __restrict__ C, int M)
{
    constexpr int K = 256;
    constexpr int TILE = 128 * 128;               // bytes per SMEM tile (128 rows x 64 bf16)
    extern __shared__ char sm[];
    uint32_t sb = smem_u32(sm);
    const uint32_t sAh = sb, sAl = sb + TILE, sBh = sb + 2 * TILE, sBl = sb + 3 * TILE;

    const int tid = threadIdx.x;
    const int wid = tid >> 5;
    const int lane = tid & 31;
    const int g = lane >> 2;            // groupID 0..7
    const int t = lane & 3;             // thread-in-group
    const int wm = wid >> 2;            // 0..1
    const int wn = wid & 3;             // 0..3
    const int m0 = blockIdx.x * 128;
    const int n0 = blockIdx.y * 128;

    float acc[4][4][4];
    #pragma unroll
    for (int i = 0; i < 4; i++)
        #pragma unroll
        for (int j = 0; j < 4; j++)
            #pragma unroll
            for (int q = 0; q < 4; q++) acc[i][j][q] = 0.f;

    uint32_t arow[4];
    uint32_t brow[4];
    #pragma unroll
    for (int mi = 0; mi < 4; mi++) arow[mi] = (uint32_t)(wm * 64 + mi * 16 + g) * 128;
    #pragma unroll
    for (int ni = 0; ni < 4; ni++) brow[ni] = (uint32_t)(wn * 32 + ni * 8 + g) * 128;

    for (int c = 0; c < 4; c++) {
        const int k0 = c * 64;
        // cooperative load: 128 rows x {Ah,Al,Bh,Bl}, 8 x 16B slots per row
        #pragma unroll
        for (int v = tid; v < 1024; v += 256) {
            int row = v >> 3, u = v & 7;
            uint32_t so = SWZ((uint32_t)(row * 128 + u * 16));
            uint4 hv = make_uint4(0, 0, 0, 0), lv = make_uint4(0, 0, 0, 0);
            if (m0 + row < M) {
                size_t gi = (size_t)(m0 + row) * K + k0 + u * 8;
                float4 fa = *(const float4*)(A + gi);
                float4 fb = *(const float4*)(A + gi + 4);
                split2(fa.x, fa.y, hv.x, lv.x);
                split2(fa.z, fa.w, hv.y, lv.y);
                split2(fb.x, fb.y, hv.z, lv.z);
                split2(fb.z, fb.w, hv.w, lv.w);
            }
            *(uint4*)(sm + so)        = hv;
            *(uint4*)(sm + TILE + so) = lv;
            size_t gb = (size_t)(n0 + row) * K + k0 + u * 8;
            *(uint4*)(sm + 2 * TILE + so) = *(const uint4*)(Bh + gb);
            *(uint4*)(sm + 3 * TILE + so) = *(const uint4*)(Bl + gb);
        }
        __syncthreads();

        #pragma unroll
        for (int ks = 0; ks < 4; ks++) {
            const uint32_t kb0 = (uint32_t)(ks * 32 + t * 4);
            const uint32_t kb1 = kb0 + 16;

            uint32_t afr[4][4];
            #pragma unroll
            for (int mi = 0; mi < 4; mi++) {
                afr[mi][0] = lds32(sAh + SWZ(arow[mi] + kb0));
                afr[mi][1] = lds32(sAh + SWZ(arow[mi] + 1024 + kb0));  // +8 rows
                afr[mi][2] = lds32(sAh + SWZ(arow[mi] + kb1));
                afr[mi][3] = lds32(sAh + SWZ(arow[mi] + 1024 + kb1));
            }
            uint32_t bfr[4][2];
            #pragma unroll
            for (int ni = 0; ni < 4; ni++) {
                bfr[ni][0] = lds32(sBh + SWZ(brow[ni] + kb0));
                bfr[ni][1] = lds32(sBh + SWZ(brow[ni] + kb1));
            }
            #pragma unroll
            for (int mi = 0; mi < 4; mi++)
                #pragma unroll
                for (int ni = 0; ni < 4; ni++) MMA_BF16(acc[mi][ni], afr[mi], bfr[ni]);
            #pragma unroll
            for (int ni = 0; ni < 4; ni++) {
                bfr[ni][0] = lds32(sBl + SWZ(brow[ni] + kb0));
                bfr[ni][1] = lds32(sBl + SWZ(brow[ni] + kb1));
            }
            #pragma unroll
            for (int mi = 0; mi < 4; mi++)
                #pragma unroll
                for (int ni = 0; ni < 4; ni++) MMA_BF16(acc[mi][ni], afr[mi], bfr[ni]);
            #pragma unroll
            for (int mi = 0; mi < 4; mi++) {
                afr[mi][0] = lds32(sAl + SWZ(arow[mi] + kb0));
                afr[mi][1] = lds32(sAl + SWZ(arow[mi] + 1024 + kb0));
                afr[mi][2] = lds32(sAl + SWZ(arow[mi] + kb1));
                afr[mi][3] = lds32(sAl + SWZ(arow[mi] + 1024 + kb1));
            }
            #pragma unroll
            for (int ni = 0; ni < 4; ni++) {
                bfr[ni][0] = lds32(sBh + SWZ(brow[ni] + kb0));
                bfr[ni][1] = lds32(sBh + SWZ(brow[ni] + kb1));
            }
            #pragma unroll
            for (int mi = 0; mi < 4; mi++)
                #pragma unroll
                for (int ni = 0; ni < 4; ni++) MMA_BF16(acc[mi][ni], afr[mi], bfr[ni]);
        }
        __syncthreads();
    }

    // epilogue: scale by dis[row] and store
    #pragma unroll
    for (int mi = 0; mi < 4; mi++) {
        int r0 = m0 + wm * 64 + mi * 16 + g;
        int r1 = r0 + 8;
        float s0 = (r0 < M) ? g_dis[r0] : 0.f;
        float s1 = (r1 < M) ? g_dis[r1] : 0.f;
        #pragma unroll
        for (int ni = 0; ni < 4; ni++) {
            int col = n0 + wn * 32 + ni * 8 + t * 2;
            if (r0 < M)
                *(float2*)(C + (size_t)r0 * NTOT + col) =
                    make_float2(acc[mi][ni][0] * s0, acc[mi][ni][1] * s0);
            if (r1 < M)
                *(float2*)(C + (size_t)r1 * NTOT + col) =
                    make_float2(acc[mi][ni][2] * s1, acc[mi][ni][3] * s1);
        }
    }
}

// ---------------- gather aggregation: out = relu(dis[n]*(self+sum) + bias), float4 ----------------
// C4 = channels/4 (64 for layer1, 32 for layer2). 128 threads/block, 128/C4 nodes per block.
template <int C4>
__global__ __launch_bounds__(128) void agg_kernel(
    const float* __restrict__ hs_, const float* __restrict__ bias_,
    float* __restrict__ out_, int N)
{
    constexpr int NPB = 128 / C4;
    int node = blockIdx.x * NPB + threadIdx.x / C4;
    int c = threadIdx.x % C4;
    if (node >= N) return;
    const float4* hs = (const float4*)hs_;
    float dn = g_dis[node];
    int s0 = g_off[node], s1 = g_off[node + 1];
    float4 a0 = hs[(size_t)node * C4 + c];     // self-loop (already *dis[node])
    float4 a1 = make_float4(0.f, 0.f, 0.f, 0.f);
    int j = s0;
    for (; j + 1 < s1; j += 2) {
        int ia = g_csr[j];
        int ib = g_csr[j + 1];
        float4 va = hs[(size_t)ia * C4 + c];
        float4 vb = hs[(size_t)ib * C4 + c];
        a0.x += va.x; a0.y += va.y; a0.z += va.z; a0.w += va.w;
        a1.x += vb.x; a1.y += vb.y; a1.z += vb.z; a1.w += vb.w;
    }
    if (j < s1) {
        float4 va = hs[(size_t)g_csr[j] * C4 + c];
        a0.x += va.x; a0.y += va.y; a0.z += va.z; a0.w += va.w;
    }
    float4 bv = ((const float4*)bias_)[c];
    float4 r;
    r.x = fmaxf(fmaf(a0.x + a1.x, dn, bv.x), 0.f);
    r.y = fmaxf(fmaf(a0.y + a1.y, dn, bv.y), 0.f);
    r.z = fmaxf(fmaf(a0.z + a1.z, dn, bv.z), 0.f);
    r.w = fmaxf(fmaf(a0.w + a1.w, dn, bv.w), 0.f);
    ((float4*)out_)[(size_t)node * C4 + c] = r;
}

// ---------------- global max pool per graph ----------------
__global__ void pool_kernel() {
    int g = blockIdx.x;
    int c = threadIdx.x;          // 0..127
    int a = g_gs[g], b = g_gs[g + 1];
    float m = -3.402823466e38f;
    int n = a;
    for (; n + 3 < b; n += 4) {
        float v0 = g_cx[(size_t)(n + 0) * HID2 + c];
        float v1 = g_cx[(size_t)(n + 1) * HID2 + c];
        float v2 = g_cx[(size_t)(n + 2) * HID2 + c];
        float v3 = g_cx[(size_t)(n + 3) * HID2 + c];
        m = fmaxf(m, fmaxf(fmaxf(v0, v1), fmaxf(v2, v3)));
    }
    for (; n < b; n++) m = fmaxf(m, g_cx[(size_t)n * HID2 + c]);
    g_px[g * HID2 + c] = m;
}

// ---------------- head ----------------
__global__ void head_kernel(const float* __restrict__ Wm, const float* __restrict__ bm,
                            float* __restrict__ out)
{
    int g = blockIdx.x;
    int d = threadIdx.x;          // 0..63
    float acc = bm[d];
    #pragma unroll 8
    for (int k = 0; k < HID2; k++)
        acc = fmaf(g_px[g * HID2 + k], Wm[k * N_DCS + d], acc);
    out[g * N_DCS + d] = acc;
}

// ---------------- launch ----------------
extern "C" void kernel_launch(void* const* d_in, const int* in_sizes, int n_in,
                              void* d_out, int out_size)
{
    const float* x     = (const float*)d_in[0];
    const int*   ei    = (const int*)  d_in[1];
    const int*   batch = (const int*)  d_in[2];
    const float* W1    = (const float*)d_in[3];
    const float* b1    = (const float*)d_in[4];
    const float* W2    = (const float*)d_in[5];
    const float* b2    = (const float*)d_in[6];
    const float* Wm    = (const float*)d_in[7];
    const float* bm    = (const float*)d_in[8];
    float* out = (float*)d_out;

    const int N = in_sizes[2];          // 50000
    const int E = in_sizes[1] / 2;      // 800000
    const int* src = ei;
    const int* dst = ei + E;

    float *h1, *bx, *h2, *cx;
    __nv_bfloat16 *w1h, *w1l, *w2h, *w2l;
    cudaGetSymbolAddress((void**)&h1, g_h1);
    cudaGetSymbolAddress((void**)&bx, g_bx);
    cudaGetSymbolAddress((void**)&h2, g_h2);
    cudaGetSymbolAddress((void**)&cx, g_cx);
    cudaGetSymbolAddress((void**)&w1h, g_w1h);
    cudaGetSymbolAddress((void**)&w1l, g_w1l);
    cudaGetSymbolAddress((void**)&w2h, g_w2h);
    cudaGetSymbolAddress((void**)&w2l, g_w2l);

    const int TB = 256;
    int gn = (N + TB - 1) / TB;
    int ge = (E + TB - 1) / TB;
    int nb = (N + 1023) / 1024;         // 49 scan blocks

    const int SMEM = 4 * 128 * 128;     // 65536 bytes
    int mtiles = (N + 127) / 128;
    cudaFuncSetAttribute(mma_gemm_kernel<HID>,
                         cudaFuncAttributeMaxDynamicSharedMemorySize, SMEM);
    cudaFuncSetAttribute(mma_gemm_kernel<HID2>,
                         cudaFuncAttributeMaxDynamicSharedMemorySize, SMEM);

    // L1: prep (zero deg + pack weights)
    prep_kernel<<<ZB + HID + HID2, 256>>>(W1, W2);
    // L2: degree histogram
    hist_kernel<<<ge, TB>>>(dst, E);
    // L3: dis = rsqrt(deg+1)
    dis_kernel<<<gn, TB>>>(N);
    // L4: layer-1 GEMM (this position gets ncu-profiled)
    {
        dim3 grid(mtiles, HID / 128);
        mma_gemm_kernel<HID><<<grid, 256, SMEM>>>(x, w1h, w1l, h1, N);
    }
    // L5-L8: CSR build
    scan_block_kernel<<<nb, 1024>>>(N);
    scan_sums_kernel<<<1, 64>>>(nb, N);
    scan_add_kernel<<<gn, TB>>>(N);
    scatter_kernel<<<ge, TB>>>(src, dst, E);
    // L9: graph boundaries
    bounds_kernel<<<gn, TB>>>(batch, N);
    // L10: layer-1 aggregation -> bx fp32
    agg_kernel<64><<<(N + 1) / 2, 128>>>(h1, b1, bx, N);
    // L11: layer-2 GEMM
    {
        dim3 grid(mtiles, HID2 / 128);
        mma_gemm_kernel<HID2><<<grid, 256, SMEM>>>(bx, w2h, w2l, h2, N);
    }
    // L12: layer-2 aggregation -> cx
    agg_kernel<32><<<(N + 3) / 4, 128>>>(h2, b2, cx, N);
    // L13-L14: pool + head
    pool_kernel<<<N_GRAPHS, HID2>>>();
    head_kernel<<<N_GRAPHS, N_DCS>>>(Wm, bm, out);
}